// round 7
// baseline (speedup 1.0000x reference)
#include <cuda_runtime.h>
#include <cstdint>

// Problem dims (fixed by the dataset)
#define BROWS 8192
#define DDIM  784
#define HDIM  500
#define CDIM  512
#define SDIM  16
#define CSDIM (CDIM * SDIM)      // 8192
#define NROWS2 (BROWS * SDIM)    // 131072
#define BK 16

// -------- scratch (no allocations allowed) ----
__device__ float g_h1[BROWS * HDIM];
__device__ float g_h2[BROWS * HDIM];
__device__ float g_cnorm[CDIM];
__device__ float g_rownorm[NROWS2];
__device__ int   g_codes[NROWS2];
__device__ float g_cand_d[4 * NROWS2];
__device__ int   g_cand_i[4 * NROWS2];

// ---------------- packed f32x2 helpers (sm_100+: fma.rn.f32x2) ----------------
__device__ __forceinline__ uint64_t pack_dup(float x) {
    uint64_t r;
    asm("mov.b64 %0, {%1, %1};" : "=l"(r) : "f"(x));
    return r;
}
__device__ __forceinline__ void ffma2(uint64_t& d, uint64_t a, uint64_t b) {
    asm("fma.rn.f32x2 %0, %1, %2, %0;" : "+l"(d) : "l"(a), "l"(b));
}
__device__ __forceinline__ float2 unpack2(uint64_t v) {
    float lo, hi;
    asm("mov.b64 {%0, %1}, %2;" : "=f"(lo), "=f"(hi) : "l"(v));
    return make_float2(lo, hi);
}

// Load operand set S from smem buffer BUF, k-index KK.
// AS_/BS_ are 2D-indexable smem arrays: AS_[buf][k][m], BS_[buf][k][n].
#define LOAD_OPS(S, BUF, KK, AS_, BS_) do {                                  \
    const float* _as = &AS_[BUF][KK][tr * 16];                               \
    ulonglong2 _v0 = *(const ulonglong2*)(_as);                              \
    ulonglong2 _v1 = *(const ulonglong2*)(_as + 4);                          \
    ulonglong2 _v2 = *(const ulonglong2*)(_as + 8);                          \
    ulonglong2 _v3 = *(const ulonglong2*)(_as + 12);                         \
    apR[S][0] = _v0.x; apR[S][1] = _v0.y; apR[S][2] = _v1.x; apR[S][3] = _v1.y; \
    apR[S][4] = _v2.x; apR[S][5] = _v2.y; apR[S][6] = _v3.x; apR[S][7] = _v3.y; \
    float4 _B0 = *(const float4*)(&BS_[BUF][KK][tc * 8]);                    \
    float4 _B1 = *(const float4*)(&BS_[BUF][KK][tc * 8 + 4]);                \
    bdR[S][0] = pack_dup(_B0.x); bdR[S][1] = pack_dup(_B0.y);                \
    bdR[S][2] = pack_dup(_B0.z); bdR[S][3] = pack_dup(_B0.w);                \
    bdR[S][4] = pack_dup(_B1.x); bdR[S][5] = pack_dup(_B1.y);                \
    bdR[S][6] = pack_dup(_B1.z); bdR[S][7] = pack_dup(_B1.w);                \
} while (0)

#define FFMA_BLOCK(S) do {                                                   \
    _Pragma("unroll")                                                        \
    for (int _p = 0; _p < 8; _p++)                                           \
        _Pragma("unroll")                                                    \
        for (int _j = 0; _j < 8; _j++)                                       \
            ffma2(acc2[_p][_j], apR[S][_p], bdR[S][_j]);                     \
} while (0)

// ============================================================================
// Codebook / obs row norms in DOUBLE (one warp per row)
// ============================================================================
__global__ void cnorm_kernel(const float* __restrict__ cb, float* __restrict__ cn) {
    int warp = (blockIdx.x * blockDim.x + threadIdx.x) >> 5;
    int lane = threadIdx.x & 31;
    if (warp >= CDIM) return;
    const float* row = cb + (size_t)warp * CDIM;
    double s = 0.0;
    for (int k = lane; k < CDIM; k += 32) { double v = (double)row[k]; s += v * v; }
    #pragma unroll
    for (int o = 16; o > 0; o >>= 1) s += __shfl_down_sync(0xffffffffu, s, o);
    if (lane == 0) cn[warp] = (float)s;
}

__global__ void rownorm_kernel(const float* __restrict__ obs, float* __restrict__ rn) {
    int warp = (blockIdx.x * blockDim.x + threadIdx.x) >> 5;
    int lane = threadIdx.x & 31;
    if (warp >= NROWS2) return;
    const float* row = obs + (size_t)warp * CDIM;
    double s = 0.0;
    for (int k = lane; k < CDIM; k += 32) { double v = (double)row[k]; s += v * v; }
    #pragma unroll
    for (int o = 16; o > 0; o >>= 1) s += __shfl_down_sync(0xffffffffu, s, o);
    if (lane == 0) rn[warp] = (float)s;
}

// ============================================================================
// BIG fp32 GEMM: 256 threads, BM=256, BN=128, BK=16, 16x8/thread, FFMA2,
// double-buffered smem + double-buffered operand REGISTERS. M % 256 == 0.
// NUMERICS: one fp32 accumulator per output, FFMA over ascending k.
// ============================================================================
template<int RELU>
__global__ __launch_bounds__(256, 1)
void gemm_big(const float* __restrict__ A, const float* __restrict__ Bm,
              const float* __restrict__ bias, float* __restrict__ C,
              int N, int K)
{
    __shared__ float As[2][BK][256];   // As[buf][k][m]
    __shared__ float Bs[2][BK][128];   // Bs[buf][k][n]

    int tid = threadIdx.x;
    int tr = tid >> 4;
    int tc = tid & 15;
    int row0 = blockIdx.y * 256;
    int col0 = blockIdx.x * 128;

    const float* Arow = A + (size_t)(row0 + tid) * K;
    int bk = tid >> 4;
    int bn = (tid & 15) * 8;
    int gbn = col0 + bn;

    uint64_t acc2[8][8];
    #pragma unroll
    for (int p = 0; p < 8; p++)
        #pragma unroll
        for (int j = 0; j < 8; j++) acc2[p][j] = 0ull;

    uint64_t apR[2][8], bdR[2][8];

    int nt = (K + BK - 1) / BK;
    const float4 f40 = make_float4(0.f, 0.f, 0.f, 0.f);
    float4 a0, a1, a2, a3, b0, b1;

    // ---- load + commit tile 0 ----
    a0 = (4  <= K) ? *(const float4*)(Arow)      : f40;
    a1 = (8  <= K) ? *(const float4*)(Arow + 4)  : f40;
    a2 = (12 <= K) ? *(const float4*)(Arow + 8)  : f40;
    a3 = (16 <= K) ? *(const float4*)(Arow + 12) : f40;
    b0 = (bk < K && gbn + 4 <= N) ? *(const float4*)(Bm + (size_t)bk * N + gbn)     : f40;
    b1 = (bk < K && gbn + 8 <= N) ? *(const float4*)(Bm + (size_t)bk * N + gbn + 4) : f40;
    As[0][0][tid] = a0.x;  As[0][1][tid] = a0.y;  As[0][2][tid] = a0.z;  As[0][3][tid] = a0.w;
    As[0][4][tid] = a1.x;  As[0][5][tid] = a1.y;  As[0][6][tid] = a1.z;  As[0][7][tid] = a1.w;
    As[0][8][tid] = a2.x;  As[0][9][tid] = a2.y;  As[0][10][tid] = a2.z; As[0][11][tid] = a2.w;
    As[0][12][tid] = a3.x; As[0][13][tid] = a3.y; As[0][14][tid] = a3.z; As[0][15][tid] = a3.w;
    *(float4*)(&Bs[0][bk][bn])     = b0;
    *(float4*)(&Bs[0][bk][bn + 4]) = b1;
    __syncthreads();

    LOAD_OPS(0, 0, 0, As, Bs);    // preload kk=0 of tile 0

    for (int t = 0; t < nt; t++) {
        int cur = t & 1;
        int kn = (t + 1) * BK;
        bool more = (t + 1 < nt);
        if (more) {
            a0 = (kn + 4  <= K) ? *(const float4*)(Arow + kn)      : f40;
            a1 = (kn + 8  <= K) ? *(const float4*)(Arow + kn + 4)  : f40;
            a2 = (kn + 12 <= K) ? *(const float4*)(Arow + kn + 8)  : f40;
            a3 = (kn + 16 <= K) ? *(const float4*)(Arow + kn + 12) : f40;
            int gk = kn + bk;
            b0 = (gk < K && gbn + 4 <= N) ? *(const float4*)(Bm + (size_t)gk * N + gbn)     : f40;
            b1 = (gk < K && gbn + 8 <= N) ? *(const float4*)(Bm + (size_t)gk * N + gbn + 4) : f40;
        }

        #pragma unroll
        for (int kk = 0; kk < BK; kk++) {
            int cs = kk & 1;
            if (kk < BK - 1) LOAD_OPS(cs ^ 1, cur, kk + 1, As, Bs);
            FFMA_BLOCK(cs);
        }

        if (more) {
            int nx = cur ^ 1;
            As[nx][0][tid] = a0.x;  As[nx][1][tid] = a0.y;  As[nx][2][tid] = a0.z;  As[nx][3][tid] = a0.w;
            As[nx][4][tid] = a1.x;  As[nx][5][tid] = a1.y;  As[nx][6][tid] = a1.z;  As[nx][7][tid] = a1.w;
            As[nx][8][tid] = a2.x;  As[nx][9][tid] = a2.y;  As[nx][10][tid] = a2.z; As[nx][11][tid] = a2.w;
            As[nx][12][tid] = a3.x; As[nx][13][tid] = a3.y; As[nx][14][tid] = a3.z; As[nx][15][tid] = a3.w;
            *(float4*)(&Bs[nx][bk][bn])     = b0;
            *(float4*)(&Bs[nx][bk][bn + 4]) = b1;
        }
        __syncthreads();
        if (more) LOAD_OPS(0, cur ^ 1, 0, As, Bs);   // preload next tile kk=0
    }

    // ---- epilogue: bias + optional relu ----
    float bb[8];
    #pragma unroll
    for (int j = 0; j < 8; j++) {
        int c = col0 + tc * 8 + j;
        bb[j] = (c < N) ? bias[c] : 0.f;
    }
    int c0 = col0 + tc * 8;
    #pragma unroll
    for (int p = 0; p < 8; p++) {
        #pragma unroll
        for (int half = 0; half < 2; half++) {
            int r = row0 + tr * 16 + p * 2 + half;
            float v[8];
            #pragma unroll
            for (int j = 0; j < 8; j++) {
                float2 u = unpack2(acc2[p][j]);
                float tv = __fadd_rn(half ? u.y : u.x, bb[j]);
                if (RELU) tv = fmaxf(tv, 0.f);
                v[j] = tv;
            }
            if (c0 + 4 <= N)
                *(float4*)(C + (size_t)r * N + c0)     = make_float4(v[0], v[1], v[2], v[3]);
            if (c0 + 8 <= N)
                *(float4*)(C + (size_t)r * N + c0 + 4) = make_float4(v[4], v[5], v[6], v[7]);
        }
    }
}

// ============================================================================
// SMALL fp32 GEMM: 128x128 block, 8x8 per thread, FFMA2. (enc1/enc2/dec2)
// ============================================================================
template<int RELU>
__global__ __launch_bounds__(256, 2)
void gemm_small(const float* __restrict__ A, const float* __restrict__ Bm,
                const float* __restrict__ bias, float* __restrict__ C,
                int N, int K)
{
    __shared__ float As[BK][132];
    __shared__ float Bs[BK][128];

    int tid = threadIdx.x;
    int tr = tid >> 4;
    int tc = tid & 15;
    int row0 = blockIdx.y * 128;
    int col0 = blockIdx.x * 128;

    uint64_t acc2[4][8];
    #pragma unroll
    for (int p = 0; p < 4; p++)
        #pragma unroll
        for (int j = 0; j < 8; j++) acc2[p][j] = 0ull;

    for (int k0 = 0; k0 < K; k0 += BK) {
        #pragma unroll
        for (int e = 0; e < 8; e++) {
            int l = tid + e * 256;
            int m = l >> 4;
            int k = l & 15;
            int gk = k0 + k;
            float v = 0.f;
            if (gk < K) v = A[(size_t)(row0 + m) * K + gk];
            As[k][m] = v;
        }
        #pragma unroll
        for (int e = 0; e < 8; e++) {
            int l = tid + e * 256;
            int k = l >> 7;
            int n = l & 127;
            int gk = k0 + k, gn = col0 + n;
            float v = 0.f;
            if (gk < K && gn < N) v = Bm[(size_t)gk * N + gn];
            Bs[k][n] = v;
        }
        __syncthreads();

        #pragma unroll
        for (int kk = 0; kk < BK; kk++) {
            ulonglong2 va0 = *(const ulonglong2*)(&As[kk][tr * 8]);
            ulonglong2 va1 = *(const ulonglong2*)(&As[kk][tr * 8 + 4]);
            uint64_t ap[4] = {va0.x, va0.y, va1.x, va1.y};
            float4 b0 = *(const float4*)(&Bs[kk][tc * 8]);
            float4 b1 = *(const float4*)(&Bs[kk][tc * 8 + 4]);
            uint64_t bd[8];
            bd[0] = pack_dup(b0.x); bd[1] = pack_dup(b0.y);
            bd[2] = pack_dup(b0.z); bd[3] = pack_dup(b0.w);
            bd[4] = pack_dup(b1.x); bd[5] = pack_dup(b1.y);
            bd[6] = pack_dup(b1.z); bd[7] = pack_dup(b1.w);
            #pragma unroll
            for (int p = 0; p < 4; p++)
                #pragma unroll
                for (int j = 0; j < 8; j++)
                    ffma2(acc2[p][j], ap[p], bd[j]);
        }
        __syncthreads();
    }

    #pragma unroll
    for (int p = 0; p < 4; p++) {
        #pragma unroll
        for (int half = 0; half < 2; half++) {
            int r = row0 + tr * 8 + p * 2 + half;
            #pragma unroll
            for (int j = 0; j < 8; j++) {
                int c = col0 + tc * 8 + j;
                if (c < N) {
                    float2 u = unpack2(acc2[p][j]);
                    float v = __fadd_rn(half ? u.y : u.x, bias[c]);
                    if (RELU) v = fmaxf(v, 0.f);
                    C[(size_t)r * N + c] = v;
                }
            }
        }
    }
}

// ============================================================================
// VQ distance GEMM: same 256-thr 16x8 pipelined mainloop; each CTA owns one
// 128-code tile (blockIdx.x) x 256 obs rows (blockIdx.y). K = 512.
// Emits per-(row, ct) argmin candidate:  d2 = fl( fl(A - fl(2*B)) + C ).
// ============================================================================
__global__ __launch_bounds__(256, 1)
void vq_gemm(const float* __restrict__ obs, const float* __restrict__ cb,
             const float* __restrict__ cnorm, const float* __restrict__ rownorm,
             float* __restrict__ cand_d, int* __restrict__ cand_i)
{
    __shared__ union {
        struct { float As[2][BK][256]; float Bs[2][BK][128]; } t;
        struct { float rv[16][256]; int ri[16][256]; } r;
    } sm;

    int tid = threadIdx.x;
    int tr = tid >> 4;
    int tc = tid & 15;
    int ct = blockIdx.x;
    int row0 = blockIdx.y * 256;
    int col0 = ct * 128;

    const float* Arow = obs + (size_t)(row0 + tid) * CDIM;
    int vcode = tid & 127;
    int vkoff = (tid >> 7) * 8;
    const float* Brow = cb + (size_t)(col0 + vcode) * CDIM + vkoff;

    uint64_t acc2[8][8];
    #pragma unroll
    for (int p = 0; p < 8; p++)
        #pragma unroll
        for (int j = 0; j < 8; j++) acc2[p][j] = 0ull;

    uint64_t apR[2][8], bdR[2][8];

    const int NT = CDIM / BK;          // 32
    float4 a0, a1, a2, a3, b0, b1;

    a0 = *(const float4*)(Arow);      a1 = *(const float4*)(Arow + 4);
    a2 = *(const float4*)(Arow + 8);  a3 = *(const float4*)(Arow + 12);
    b0 = *(const float4*)(Brow);      b1 = *(const float4*)(Brow + 4);
    sm.t.As[0][0][tid] = a0.x;  sm.t.As[0][1][tid] = a0.y;  sm.t.As[0][2][tid] = a0.z;  sm.t.As[0][3][tid] = a0.w;
    sm.t.As[0][4][tid] = a1.x;  sm.t.As[0][5][tid] = a1.y;  sm.t.As[0][6][tid] = a1.z;  sm.t.As[0][7][tid] = a1.w;
    sm.t.As[0][8][tid] = a2.x;  sm.t.As[0][9][tid] = a2.y;  sm.t.As[0][10][tid] = a2.z; sm.t.As[0][11][tid] = a2.w;
    sm.t.As[0][12][tid] = a3.x; sm.t.As[0][13][tid] = a3.y; sm.t.As[0][14][tid] = a3.z; sm.t.As[0][15][tid] = a3.w;
    sm.t.Bs[0][vkoff+0][vcode] = b0.x; sm.t.Bs[0][vkoff+1][vcode] = b0.y;
    sm.t.Bs[0][vkoff+2][vcode] = b0.z; sm.t.Bs[0][vkoff+3][vcode] = b0.w;
    sm.t.Bs[0][vkoff+4][vcode] = b1.x; sm.t.Bs[0][vkoff+5][vcode] = b1.y;
    sm.t.Bs[0][vkoff+6][vcode] = b1.z; sm.t.Bs[0][vkoff+7][vcode] = b1.w;
    __syncthreads();

    LOAD_OPS(0, 0, 0, sm.t.As, sm.t.Bs);

    for (int t = 0; t < NT; t++) {
        int cur = t & 1;
        int kn = (t + 1) * BK;
        bool more = (t + 1 < NT);
        if (more) {
            a0 = *(const float4*)(Arow + kn);      a1 = *(const float4*)(Arow + kn + 4);
            a2 = *(const float4*)(Arow + kn + 8);  a3 = *(const float4*)(Arow + kn + 12);
            b0 = *(const float4*)(Brow + kn);      b1 = *(const float4*)(Brow + kn + 4);
        }

        #pragma unroll
        for (int kk = 0; kk < BK; kk++) {
            int cs = kk & 1;
            if (kk < BK - 1) LOAD_OPS(cs ^ 1, cur, kk + 1, sm.t.As, sm.t.Bs);
            FFMA_BLOCK(cs);
        }

        if (more) {
            int nx = cur ^ 1;
            sm.t.As[nx][0][tid] = a0.x;  sm.t.As[nx][1][tid] = a0.y;  sm.t.As[nx][2][tid] = a0.z;  sm.t.As[nx][3][tid] = a0.w;
            sm.t.As[nx][4][tid] = a1.x;  sm.t.As[nx][5][tid] = a1.y;  sm.t.As[nx][6][tid] = a1.z;  sm.t.As[nx][7][tid] = a1.w;
            sm.t.As[nx][8][tid] = a2.x;  sm.t.As[nx][9][tid] = a2.y;  sm.t.As[nx][10][tid] = a2.z; sm.t.As[nx][11][tid] = a2.w;
            sm.t.As[nx][12][tid] = a3.x; sm.t.As[nx][13][tid] = a3.y; sm.t.As[nx][14][tid] = a3.z; sm.t.As[nx][15][tid] = a3.w;
            sm.t.Bs[nx][vkoff+0][vcode] = b0.x; sm.t.Bs[nx][vkoff+1][vcode] = b0.y;
            sm.t.Bs[nx][vkoff+2][vcode] = b0.z; sm.t.Bs[nx][vkoff+3][vcode] = b0.w;
            sm.t.Bs[nx][vkoff+4][vcode] = b1.x; sm.t.Bs[nx][vkoff+5][vcode] = b1.y;
            sm.t.Bs[nx][vkoff+6][vcode] = b1.z; sm.t.Bs[nx][vkoff+7][vcode] = b1.w;
        }
        __syncthreads();
        if (more) LOAD_OPS(0, cur ^ 1, 0, sm.t.As, sm.t.Bs);
    }

    // ---- d2 + per-thread argmin over this tile's 8 codes x 16 rows ----
    float best[16];
    int   bidx[16];
    #pragma unroll
    for (int i = 0; i < 16; i++) { best[i] = 3.4e38f; bidx[i] = 0; }

    #pragma unroll
    for (int j = 0; j < 8; j++) {
        int code = col0 + tc * 8 + j;
        float cn = cnorm[code];
        #pragma unroll
        for (int p = 0; p < 8; p++) {
            float2 u = unpack2(acc2[p][j]);
            #pragma unroll
            for (int half = 0; half < 2; half++) {
                int i = p * 2 + half;
                float An = rownorm[row0 + tr * 16 + i];
                float twob = __fmul_rn(2.0f, half ? u.y : u.x);
                float t2   = __fadd_rn(An, -twob);
                float d    = __fadd_rn(t2, cn);
                if (d < best[i]) { best[i] = d; bidx[i] = code; }
            }
        }
    }

    // cross-tc reduction (overlay union; mainloop synced after last tile)
    #pragma unroll
    for (int i = 0; i < 16; i++) {
        sm.r.rv[tc][tr * 16 + i] = best[i];
        sm.r.ri[tc][tr * 16 + i] = bidx[i];
    }
    __syncthreads();
    {
        float bv = sm.r.rv[0][tid];
        int   bi = sm.r.ri[0][tid];
        #pragma unroll
        for (int t = 1; t < 16; t++) {
            float v = sm.r.rv[t][tid];
            int  ix = sm.r.ri[t][tid];
            if (v < bv || (v == bv && ix < bi)) { bv = v; bi = ix; }
        }
        cand_d[(size_t)ct * NROWS2 + row0 + tid] = bv;
        cand_i[(size_t)ct * NROWS2 + row0 + tid] = bi;
    }
}

// ============================================================================
// Reduce 4 candidates per row -> final code
// ============================================================================
__global__ void vq_reduce_kernel(const float* __restrict__ cand_d,
                                 const int* __restrict__ cand_i,
                                 int* __restrict__ codes)
{
    int row = blockIdx.x * 256 + threadIdx.x;
    float bv = cand_d[row];
    int   bi = cand_i[row];
    #pragma unroll
    for (int ct = 1; ct < 4; ct++) {
        float v = cand_d[(size_t)ct * NROWS2 + row];
        int  ix = cand_i[(size_t)ct * NROWS2 + row];
        if (v < bv || (v == bv && ix < bi)) { bv = v; bi = ix; }
    }
    codes[row] = bi;
}

// ============================================================================
// latent[row] = codebook[codes[row]]  (2 rows per 256-thread block)
// ============================================================================
__global__ void gather_latent_kernel(const int* __restrict__ codes,
                                     const float* __restrict__ cb,
                                     float* __restrict__ latent)
{
    int row  = blockIdx.x * 2 + (threadIdx.x >> 7);
    int lane = threadIdx.x & 127;
    int c = codes[row];
    const float4* src = (const float4*)(cb + (size_t)c * CDIM);
    float4* dst = (float4*)(latent + (size_t)row * CDIM);
    dst[lane] = src[lane];
}

// ============================================================================
// launch
// ============================================================================
extern "C" void kernel_launch(void* const* d_in, const int* in_sizes, int n_in,
                              void* d_out, int out_size)
{
    const float* x    = (const float*)d_in[0];
    const float* ew1  = (const float*)d_in[1];
    const float* eb1  = (const float*)d_in[2];
    const float* ew2  = (const float*)d_in[3];
    const float* eb2  = (const float*)d_in[4];
    const float* ew3  = (const float*)d_in[5];
    const float* eb3  = (const float*)d_in[6];
    const float* cb   = (const float*)d_in[7];
    const float* dw1  = (const float*)d_in[8];
    const float* db1  = (const float*)d_in[9];
    const float* dw2  = (const float*)d_in[10];
    const float* db2  = (const float*)d_in[11];

    float* out        = (float*)d_out;
    float* out_recon  = out;                                     // [8192, 784]
    float* out_obs    = out + (size_t)BROWS * DDIM;              // [131072, 512]
    float* out_latent = out_obs + (size_t)BROWS * CSDIM;         // [131072, 512]

    float *h1, *h2, *cn, *rn, *cd; int *codes, *ci;
    cudaGetSymbolAddress((void**)&h1, g_h1);
    cudaGetSymbolAddress((void**)&h2, g_h2);
    cudaGetSymbolAddress((void**)&cn, g_cnorm);
    cudaGetSymbolAddress((void**)&rn, g_rownorm);
    cudaGetSymbolAddress((void**)&cd, g_cand_d);
    cudaGetSymbolAddress((void**)&ci, g_cand_i);
    cudaGetSymbolAddress((void**)&codes, g_codes);

    // codebook row norms (double-accurate)
    cnorm_kernel<<<CDIM / 8, 256>>>(cb, cn);

    // encoder
    gemm_small<1><<<dim3(4, 64), 256>>>(x,  ew1, eb1, h1, HDIM, DDIM);
    gemm_small<1><<<dim3(4, 64), 256>>>(h1, ew2, eb2, h2, HDIM, HDIM);
    gemm_big<0><<<dim3(64, 32), 256>>>(h2, ew3, eb3, out_obs, CSDIM, HDIM);

    // obs row norms (double-accurate), then vector quantization
    rownorm_kernel<<<NROWS2 / 8, 256>>>(out_obs, rn);
    vq_gemm<<<dim3(4, NROWS2 / 256), 256>>>(out_obs, cb, cn, rn, cd, ci);
    vq_reduce_kernel<<<NROWS2 / 256, 256>>>(cd, ci, codes);
    gather_latent_kernel<<<NROWS2 / 2, 256>>>(codes, cb, out_latent);

    // decoder
    gemm_big<1><<<dim3(4, 32), 256>>>(out_latent, dw1, db1, h1, HDIM, CSDIM);
    gemm_small<0><<<dim3(7, 64), 256>>>(h1, dw2, db2, out_recon, DDIM, HDIM);
}

// round 9
// speedup vs baseline: 1.4518x; 1.4518x over previous
#include <cuda_runtime.h>
#include <cstdint>

// Problem dims (fixed by the dataset)
#define BROWS 8192
#define DDIM  784
#define HDIM  500
#define CDIM  512
#define SDIM  16
#define CSDIM (CDIM * SDIM)      // 8192
#define NROWS2 (BROWS * SDIM)    // 131072
#define BK 16

// -------- scratch (no allocations allowed) ----
__device__ float g_h1[BROWS * HDIM];
__device__ float g_cnorm[CDIM];
__device__ float g_rownorm[NROWS2];
__device__ int   g_codes[NROWS2];
__device__ float g_cand_d[4 * NROWS2];
__device__ int   g_cand_i[4 * NROWS2];
__device__ float g_table[SDIM * CDIM * 512];   // T[s][c][n], n padded 500->512 (16.8 MB)
__device__ float g_h2[BROWS * HDIM];

// ---------------- packed f32x2 helpers (sm_100+: fma.rn.f32x2) ----------------
__device__ __forceinline__ uint64_t pack_dup(float x) {
    uint64_t r;
    asm("mov.b64 %0, {%1, %1};" : "=l"(r) : "f"(x));
    return r;
}
__device__ __forceinline__ void ffma2(uint64_t& d, uint64_t a, uint64_t b) {
    asm("fma.rn.f32x2 %0, %1, %2, %0;" : "+l"(d) : "l"(a), "l"(b));
}
__device__ __forceinline__ float2 unpack2(uint64_t v) {
    float lo, hi;
    asm("mov.b64 {%0, %1}, %2;" : "=f"(lo), "=f"(hi) : "l"(v));
    return make_float2(lo, hi);
}

// ============================================================================
// Codebook / obs row norms in DOUBLE (one warp per row)
// ============================================================================
__global__ void cnorm_kernel(const float* __restrict__ cb, float* __restrict__ cn) {
    int warp = (blockIdx.x * blockDim.x + threadIdx.x) >> 5;
    int lane = threadIdx.x & 31;
    if (warp >= CDIM) return;
    const float* row = cb + (size_t)warp * CDIM;
    double s = 0.0;
    for (int k = lane; k < CDIM; k += 32) { double v = (double)row[k]; s += v * v; }
    #pragma unroll
    for (int o = 16; o > 0; o >>= 1) s += __shfl_down_sync(0xffffffffu, s, o);
    if (lane == 0) cn[warp] = (float)s;
}

__global__ void rownorm_kernel(const float* __restrict__ obs, float* __restrict__ rn) {
    int warp = (blockIdx.x * blockDim.x + threadIdx.x) >> 5;
    int lane = threadIdx.x & 31;
    if (warp >= NROWS2) return;
    const float* row = obs + (size_t)warp * CDIM;
    double s = 0.0;
    for (int k = lane; k < CDIM; k += 32) { double v = (double)row[k]; s += v * v; }
    #pragma unroll
    for (int o = 16; o > 0; o >>= 1) s += __shfl_down_sync(0xffffffffu, s, o);
    if (lane == 0) rn[warp] = (float)s;
}

// ============================================================================
// BIG fp32 GEMM: 256 threads, BM=256, BN=128, BK=16, 16x8/thread, FFMA2,
// double-buffered smem (R6 version — best measured). M % 256 == 0.
// NUMERICS: one fp32 accumulator per output, FFMA over ascending k.
// ============================================================================
template<int RELU>
__global__ __launch_bounds__(256, 1)
void gemm_big(const float* __restrict__ A, const float* __restrict__ Bm,
              const float* __restrict__ bias, float* __restrict__ C,
              int N, int K)
{
    __shared__ float As[2][BK][256];   // As[buf][k][m]
    __shared__ float Bs[2][BK][128];   // Bs[buf][k][n]

    int tid = threadIdx.x;
    int tr = tid >> 4;
    int tc = tid & 15;
    int row0 = blockIdx.y * 256;
    int col0 = blockIdx.x * 128;

    const float* Arow = A + (size_t)(row0 + tid) * K;
    int bk = tid >> 4;
    int bn = (tid & 15) * 8;
    int gbn = col0 + bn;

    uint64_t acc2[8][8];
    #pragma unroll
    for (int p = 0; p < 8; p++)
        #pragma unroll
        for (int j = 0; j < 8; j++) acc2[p][j] = 0ull;

    int nt = (K + BK - 1) / BK;
    const float4 f40 = make_float4(0.f, 0.f, 0.f, 0.f);
    float4 a0, a1, a2, a3, b0, b1;

    a0 = (4  <= K) ? *(const float4*)(Arow)      : f40;
    a1 = (8  <= K) ? *(const float4*)(Arow + 4)  : f40;
    a2 = (12 <= K) ? *(const float4*)(Arow + 8)  : f40;
    a3 = (16 <= K) ? *(const float4*)(Arow + 12) : f40;
    b0 = (bk < K && gbn + 4 <= N) ? *(const float4*)(Bm + (size_t)bk * N + gbn)     : f40;
    b1 = (bk < K && gbn + 8 <= N) ? *(const float4*)(Bm + (size_t)bk * N + gbn + 4) : f40;
    As[0][0][tid] = a0.x;  As[0][1][tid] = a0.y;  As[0][2][tid] = a0.z;  As[0][3][tid] = a0.w;
    As[0][4][tid] = a1.x;  As[0][5][tid] = a1.y;  As[0][6][tid] = a1.z;  As[0][7][tid] = a1.w;
    As[0][8][tid] = a2.x;  As[0][9][tid] = a2.y;  As[0][10][tid] = a2.z; As[0][11][tid] = a2.w;
    As[0][12][tid] = a3.x; As[0][13][tid] = a3.y; As[0][14][tid] = a3.z; As[0][15][tid] = a3.w;
    *(float4*)(&Bs[0][bk][bn])     = b0;
    *(float4*)(&Bs[0][bk][bn + 4]) = b1;
    __syncthreads();

    for (int t = 0; t < nt; t++) {
        int cur = t & 1;
        int kn = (t + 1) * BK;
        bool more = (t + 1 < nt);
        if (more) {
            a0 = (kn + 4  <= K) ? *(const float4*)(Arow + kn)      : f40;
            a1 = (kn + 8  <= K) ? *(const float4*)(Arow + kn + 4)  : f40;
            a2 = (kn + 12 <= K) ? *(const float4*)(Arow + kn + 8)  : f40;
            a3 = (kn + 16 <= K) ? *(const float4*)(Arow + kn + 12) : f40;
            int gk = kn + bk;
            b0 = (gk < K && gbn + 4 <= N) ? *(const float4*)(Bm + (size_t)gk * N + gbn)     : f40;
            b1 = (gk < K && gbn + 8 <= N) ? *(const float4*)(Bm + (size_t)gk * N + gbn + 4) : f40;
        }

        #pragma unroll
        for (int kk = 0; kk < BK; kk++) {
            const float* as = &As[cur][kk][tr * 16];
            ulonglong2 v0 = *(const ulonglong2*)(as);
            ulonglong2 v1 = *(const ulonglong2*)(as + 4);
            ulonglong2 v2 = *(const ulonglong2*)(as + 8);
            ulonglong2 v3 = *(const ulonglong2*)(as + 12);
            uint64_t ap[8] = {v0.x, v0.y, v1.x, v1.y, v2.x, v2.y, v3.x, v3.y};
            float4 B0 = *(const float4*)(&Bs[cur][kk][tc * 8]);
            float4 B1 = *(const float4*)(&Bs[cur][kk][tc * 8 + 4]);
            uint64_t bd[8];
            bd[0] = pack_dup(B0.x); bd[1] = pack_dup(B0.y);
            bd[2] = pack_dup(B0.z); bd[3] = pack_dup(B0.w);
            bd[4] = pack_dup(B1.x); bd[5] = pack_dup(B1.y);
            bd[6] = pack_dup(B1.z); bd[7] = pack_dup(B1.w);
            #pragma unroll
            for (int p = 0; p < 8; p++)
                #pragma unroll
                for (int j = 0; j < 8; j++)
                    ffma2(acc2[p][j], ap[p], bd[j]);
        }

        if (more) {
            int nx = cur ^ 1;
            As[nx][0][tid] = a0.x;  As[nx][1][tid] = a0.y;  As[nx][2][tid] = a0.z;  As[nx][3][tid] = a0.w;
            As[nx][4][tid] = a1.x;  As[nx][5][tid] = a1.y;  As[nx][6][tid] = a1.z;  As[nx][7][tid] = a1.w;
            As[nx][8][tid] = a2.x;  As[nx][9][tid] = a2.y;  As[nx][10][tid] = a2.z; As[nx][11][tid] = a2.w;
            As[nx][12][tid] = a3.x; As[nx][13][tid] = a3.y; As[nx][14][tid] = a3.z; As[nx][15][tid] = a3.w;
            *(float4*)(&Bs[nx][bk][bn])     = b0;
            *(float4*)(&Bs[nx][bk][bn + 4]) = b1;
        }
        __syncthreads();
    }

    float bb[8];
    #pragma unroll
    for (int j = 0; j < 8; j++) {
        int c = col0 + tc * 8 + j;
        bb[j] = (c < N) ? bias[c] : 0.f;
    }
    int c0 = col0 + tc * 8;
    #pragma unroll
    for (int p = 0; p < 8; p++) {
        #pragma unroll
        for (int half = 0; half < 2; half++) {
            int r = row0 + tr * 16 + p * 2 + half;
            float v[8];
            #pragma unroll
            for (int j = 0; j < 8; j++) {
                float2 u = unpack2(acc2[p][j]);
                float tv = __fadd_rn(half ? u.y : u.x, bb[j]);
                if (RELU) tv = fmaxf(tv, 0.f);
                v[j] = tv;
            }
            if (c0 + 4 <= N)
                *(float4*)(C + (size_t)r * N + c0)     = make_float4(v[0], v[1], v[2], v[3]);
            if (c0 + 8 <= N)
                *(float4*)(C + (size_t)r * N + c0 + 4) = make_float4(v[4], v[5], v[6], v[7]);
        }
    }
}

// ============================================================================
// SMALL fp32 GEMM: 128x128 block, 8x8 per thread, FFMA2. (enc1/enc2/dec2)
// LDC: output row stride (LDC==0 -> use N). BIAS: add bias if nonzero.
// ============================================================================
template<int RELU, int HAS_BIAS>
__global__ __launch_bounds__(256, 2)
void gemm_small(const float* __restrict__ A, const float* __restrict__ Bm,
                const float* __restrict__ bias, float* __restrict__ C,
                int N, int K, int ldc)
{
    __shared__ float As[BK][132];
    __shared__ float Bs[BK][128];

    int tid = threadIdx.x;
    int tr = tid >> 4;
    int tc = tid & 15;
    int row0 = blockIdx.y * 128;
    int col0 = blockIdx.x * 128;

    uint64_t acc2[4][8];
    #pragma unroll
    for (int p = 0; p < 4; p++)
        #pragma unroll
        for (int j = 0; j < 8; j++) acc2[p][j] = 0ull;

    for (int k0 = 0; k0 < K; k0 += BK) {
        #pragma unroll
        for (int e = 0; e < 8; e++) {
            int l = tid + e * 256;
            int m = l >> 4;
            int k = l & 15;
            int gk = k0 + k;
            float v = 0.f;
            if (gk < K) v = A[(size_t)(row0 + m) * K + gk];
            As[k][m] = v;
        }
        #pragma unroll
        for (int e = 0; e < 8; e++) {
            int l = tid + e * 256;
            int k = l >> 7;
            int n = l & 127;
            int gk = k0 + k, gn = col0 + n;
            float v = 0.f;
            if (gk < K && gn < N) v = Bm[(size_t)gk * N + gn];
            Bs[k][n] = v;
        }
        __syncthreads();

        #pragma unroll
        for (int kk = 0; kk < BK; kk++) {
            ulonglong2 va0 = *(const ulonglong2*)(&As[kk][tr * 8]);
            ulonglong2 va1 = *(const ulonglong2*)(&As[kk][tr * 8 + 4]);
            uint64_t ap[4] = {va0.x, va0.y, va1.x, va1.y};
            float4 b0 = *(const float4*)(&Bs[kk][tc * 8]);
            float4 b1 = *(const float4*)(&Bs[kk][tc * 8 + 4]);
            uint64_t bd[8];
            bd[0] = pack_dup(b0.x); bd[1] = pack_dup(b0.y);
            bd[2] = pack_dup(b0.z); bd[3] = pack_dup(b0.w);
            bd[4] = pack_dup(b1.x); bd[5] = pack_dup(b1.y);
            bd[6] = pack_dup(b1.z); bd[7] = pack_dup(b1.w);
            #pragma unroll
            for (int p = 0; p < 4; p++)
                #pragma unroll
                for (int j = 0; j < 8; j++)
                    ffma2(acc2[p][j], ap[p], bd[j]);
        }
        __syncthreads();
    }

    #pragma unroll
    for (int p = 0; p < 4; p++) {
        #pragma unroll
        for (int half = 0; half < 2; half++) {
            int r = row0 + tr * 8 + p * 2 + half;
            #pragma unroll
            for (int j = 0; j < 8; j++) {
                int c = col0 + tc * 8 + j;
                if (c < N) {
                    float2 u = unpack2(acc2[p][j]);
                    float v = half ? u.y : u.x;
                    if (HAS_BIAS) v = __fadd_rn(v, bias[c]);
                    if (RELU) v = fmaxf(v, 0.f);
                    C[(size_t)r * ldc + c] = v;
                }
            }
        }
    }
}

// ============================================================================
// Decoder table: T[s][c][n] = sum_k cb[c][k] * dec_w1[(s*512+k)*500 + n]
// One 128x128 tile per block; blockIdx.z = s. Output stride 512 (padded).
// ============================================================================
__global__ __launch_bounds__(256, 2)
void table_gemm(const float* __restrict__ cb, const float* __restrict__ dw1,
                float* __restrict__ table)
{
    const float* A = cb;                              // [512, 512]
    const float* Bm = dw1 + (size_t)blockIdx.z * CDIM * HDIM;  // [512, 500] slice
    float* C = table + (size_t)blockIdx.z * CDIM * 512;

    __shared__ float As[BK][132];
    __shared__ float Bs[BK][128];

    int tid = threadIdx.x;
    int tr = tid >> 4;
    int tc = tid & 15;
    int row0 = blockIdx.y * 128;
    int col0 = blockIdx.x * 128;

    uint64_t acc2[4][8];
    #pragma unroll
    for (int p = 0; p < 4; p++)
        #pragma unroll
        for (int j = 0; j < 8; j++) acc2[p][j] = 0ull;

    for (int k0 = 0; k0 < CDIM; k0 += BK) {
        #pragma unroll
        for (int e = 0; e < 8; e++) {
            int l = tid + e * 256;
            int m = l >> 4;
            int k = l & 15;
            As[k][m] = A[(size_t)(row0 + m) * CDIM + k0 + k];
        }
        #pragma unroll
        for (int e = 0; e < 8; e++) {
            int l = tid + e * 256;
            int k = l >> 7;
            int n = l & 127;
            int gn = col0 + n;
            Bs[k][n] = (gn < HDIM) ? Bm[(size_t)(k0 + k) * HDIM + gn] : 0.f;
        }
        __syncthreads();

        #pragma unroll
        for (int kk = 0; kk < BK; kk++) {
            ulonglong2 va0 = *(const ulonglong2*)(&As[kk][tr * 8]);
            ulonglong2 va1 = *(const ulonglong2*)(&As[kk][tr * 8 + 4]);
            uint64_t ap[4] = {va0.x, va0.y, va1.x, va1.y};
            float4 b0 = *(const float4*)(&Bs[kk][tc * 8]);
            float4 b1 = *(const float4*)(&Bs[kk][tc * 8 + 4]);
            uint64_t bd[8];
            bd[0] = pack_dup(b0.x); bd[1] = pack_dup(b0.y);
            bd[2] = pack_dup(b0.z); bd[3] = pack_dup(b0.w);
            bd[4] = pack_dup(b1.x); bd[5] = pack_dup(b1.y);
            bd[6] = pack_dup(b1.z); bd[7] = pack_dup(b1.w);
            #pragma unroll
            for (int p = 0; p < 4; p++)
                #pragma unroll
                for (int j = 0; j < 8; j++)
                    ffma2(acc2[p][j], ap[p], bd[j]);
        }
        __syncthreads();
    }

    #pragma unroll
    for (int p = 0; p < 4; p++) {
        #pragma unroll
        for (int half = 0; half < 2; half++) {
            int r = row0 + tr * 8 + p * 2 + half;
            #pragma unroll
            for (int j = 0; j < 8; j++) {
                int c = col0 + tc * 8 + j;
                if (c < HDIM) {
                    float2 u = unpack2(acc2[p][j]);
                    C[(size_t)r * 512 + c] = half ? u.y : u.x;
                }
            }
        }
    }
}

// ============================================================================
// dec1 via table gather-sum: h1[b,n] = relu(db1[n] + sum_s T[s, codes[b,s], n])
// 256 threads = 2 rows x 128 float4-lanes (125 used). Table is L2-resident.
// ============================================================================
__global__ __launch_bounds__(256, 8)
void dec1_gather(const int* __restrict__ codes, const float* __restrict__ table,
                 const float* __restrict__ db1, float* __restrict__ h1)
{
    int b = blockIdx.x * 2 + (threadIdx.x >> 7);
    int t = threadIdx.x & 127;

    __shared__ int cds[2][16];
    if ((threadIdx.x & 127) < 16)
        cds[threadIdx.x >> 7][threadIdx.x & 127] = codes[b * 16 + (threadIdx.x & 127)];
    __syncthreads();

    if (t >= 125) return;
    const int* cd = cds[threadIdx.x >> 7];

    float4 acc = *(const float4*)(db1 + t * 4);
    #pragma unroll
    for (int s = 0; s < 16; s++) {
        const float4* row = (const float4*)(table + (((size_t)s * CDIM + cd[s]) << 9));
        float4 v = row[t];
        acc.x += v.x; acc.y += v.y; acc.z += v.z; acc.w += v.w;
    }
    acc.x = fmaxf(acc.x, 0.f); acc.y = fmaxf(acc.y, 0.f);
    acc.z = fmaxf(acc.z, 0.f); acc.w = fmaxf(acc.w, 0.f);
    // h1 row stride = 500 floats = 2000 B (16B-multiple) -> float4 store OK
    *(float4*)(h1 + (size_t)b * HDIM + t * 4) = acc;
}

// ============================================================================
// VQ distance GEMM (R6 version): each CTA owns one 128-code tile x 256 rows.
// Emits per-(row, ct) argmin candidate:  d2 = fl( fl(A - fl(2*B)) + C ).
// ============================================================================
__global__ __launch_bounds__(256, 1)
void vq_gemm(const float* __restrict__ obs, const float* __restrict__ cb,
             const float* __restrict__ cnorm, const float* __restrict__ rownorm,
             float* __restrict__ cand_d, int* __restrict__ cand_i)
{
    __shared__ union {
        struct { float As[2][BK][256]; float Bs[2][BK][128]; } t;
        struct { float rv[16][256]; int ri[16][256]; } r;
    } sm;

    int tid = threadIdx.x;
    int tr = tid >> 4;
    int tc = tid & 15;
    int ct = blockIdx.x;
    int row0 = blockIdx.y * 256;
    int col0 = ct * 128;

    const float* Arow = obs + (size_t)(row0 + tid) * CDIM;
    int vcode = tid & 127;
    int vkoff = (tid >> 7) * 8;
    const float* Brow = cb + (size_t)(col0 + vcode) * CDIM + vkoff;

    uint64_t acc2[8][8];
    #pragma unroll
    for (int p = 0; p < 8; p++)
        #pragma unroll
        for (int j = 0; j < 8; j++) acc2[p][j] = 0ull;

    const int NT = CDIM / BK;          // 32
    float4 a0, a1, a2, a3, b0, b1;

    a0 = *(const float4*)(Arow);      a1 = *(const float4*)(Arow + 4);
    a2 = *(const float4*)(Arow + 8);  a3 = *(const float4*)(Arow + 12);
    b0 = *(const float4*)(Brow);      b1 = *(const float4*)(Brow + 4);
    sm.t.As[0][0][tid] = a0.x;  sm.t.As[0][1][tid] = a0.y;  sm.t.As[0][2][tid] = a0.z;  sm.t.As[0][3][tid] = a0.w;
    sm.t.As[0][4][tid] = a1.x;  sm.t.As[0][5][tid] = a1.y;  sm.t.As[0][6][tid] = a1.z;  sm.t.As[0][7][tid] = a1.w;
    sm.t.As[0][8][tid] = a2.x;  sm.t.As[0][9][tid] = a2.y;  sm.t.As[0][10][tid] = a2.z; sm.t.As[0][11][tid] = a2.w;
    sm.t.As[0][12][tid] = a3.x; sm.t.As[0][13][tid] = a3.y; sm.t.As[0][14][tid] = a3.z; sm.t.As[0][15][tid] = a3.w;
    sm.t.Bs[0][vkoff+0][vcode] = b0.x; sm.t.Bs[0][vkoff+1][vcode] = b0.y;
    sm.t.Bs[0][vkoff+2][vcode] = b0.z; sm.t.Bs[0][vkoff+3][vcode] = b0.w;
    sm.t.Bs[0][vkoff+4][vcode] = b1.x; sm.t.Bs[0][vkoff+5][vcode] = b1.y;
    sm.t.Bs[0][vkoff+6][vcode] = b1.z; sm.t.Bs[0][vkoff+7][vcode] = b1.w;
    __syncthreads();

    for (int t = 0; t < NT; t++) {
        int cur = t & 1;
        int kn = (t + 1) * BK;
        bool more = (t + 1 < NT);
        if (more) {
            a0 = *(const float4*)(Arow + kn);      a1 = *(const float4*)(Arow + kn + 4);
            a2 = *(const float4*)(Arow + kn + 8);  a3 = *(const float4*)(Arow + kn + 12);
            b0 = *(const float4*)(Brow + kn);      b1 = *(const float4*)(Brow + kn + 4);
        }

        #pragma unroll
        for (int kk = 0; kk < BK; kk++) {
            const float* as = &sm.t.As[cur][kk][tr * 16];
            ulonglong2 v0 = *(const ulonglong2*)(as);
            ulonglong2 v1 = *(const ulonglong2*)(as + 4);
            ulonglong2 v2 = *(const ulonglong2*)(as + 8);
            ulonglong2 v3 = *(const ulonglong2*)(as + 12);
            uint64_t ap[8] = {v0.x, v0.y, v1.x, v1.y, v2.x, v2.y, v3.x, v3.y};
            float4 B0 = *(const float4*)(&sm.t.Bs[cur][kk][tc * 8]);
            float4 B1 = *(const float4*)(&sm.t.Bs[cur][kk][tc * 8 + 4]);
            uint64_t bd[8];
            bd[0] = pack_dup(B0.x); bd[1] = pack_dup(B0.y);
            bd[2] = pack_dup(B0.z); bd[3] = pack_dup(B0.w);
            bd[4] = pack_dup(B1.x); bd[5] = pack_dup(B1.y);
            bd[6] = pack_dup(B1.z); bd[7] = pack_dup(B1.w);
            #pragma unroll
            for (int p = 0; p < 8; p++)
                #pragma unroll
                for (int j = 0; j < 8; j++)
                    ffma2(acc2[p][j], ap[p], bd[j]);
        }

        if (more) {
            int nx = cur ^ 1;
            sm.t.As[nx][0][tid] = a0.x;  sm.t.As[nx][1][tid] = a0.y;  sm.t.As[nx][2][tid] = a0.z;  sm.t.As[nx][3][tid] = a0.w;
            sm.t.As[nx][4][tid] = a1.x;  sm.t.As[nx][5][tid] = a1.y;  sm.t.As[nx][6][tid] = a1.z;  sm.t.As[nx][7][tid] = a1.w;
            sm.t.As[nx][8][tid] = a2.x;  sm.t.As[nx][9][tid] = a2.y;  sm.t.As[nx][10][tid] = a2.z; sm.t.As[nx][11][tid] = a2.w;
            sm.t.As[nx][12][tid] = a3.x; sm.t.As[nx][13][tid] = a3.y; sm.t.As[nx][14][tid] = a3.z; sm.t.As[nx][15][tid] = a3.w;
            sm.t.Bs[nx][vkoff+0][vcode] = b0.x; sm.t.Bs[nx][vkoff+1][vcode] = b0.y;
            sm.t.Bs[nx][vkoff+2][vcode] = b0.z; sm.t.Bs[nx][vkoff+3][vcode] = b0.w;
            sm.t.Bs[nx][vkoff+4][vcode] = b1.x; sm.t.Bs[nx][vkoff+5][vcode] = b1.y;
            sm.t.Bs[nx][vkoff+6][vcode] = b1.z; sm.t.Bs[nx][vkoff+7][vcode] = b1.w;
        }
        __syncthreads();
    }

    // ---- d2 + per-thread argmin over this tile's 8 codes x 16 rows ----
    float best[16];
    int   bidx[16];
    #pragma unroll
    for (int i = 0; i < 16; i++) { best[i] = 3.4e38f; bidx[i] = 0; }

    #pragma unroll
    for (int j = 0; j < 8; j++) {
        int code = col0 + tc * 8 + j;
        float cn = cnorm[code];
        #pragma unroll
        for (int p = 0; p < 8; p++) {
            float2 u = unpack2(acc2[p][j]);
            #pragma unroll
            for (int half = 0; half < 2; half++) {
                int i = p * 2 + half;
                float An = rownorm[row0 + tr * 16 + i];
                float twob = __fmul_rn(2.0f, half ? u.y : u.x);
                float t2   = __fadd_rn(An, -twob);
                float d    = __fadd_rn(t2, cn);
                if (d < best[i]) { best[i] = d; bidx[i] = code; }
            }
        }
    }

    #pragma unroll
    for (int i = 0; i < 16; i++) {
        sm.r.rv[tc][tr * 16 + i] = best[i];
        sm.r.ri[tc][tr * 16 + i] = bidx[i];
    }
    __syncthreads();
    {
        float bv = sm.r.rv[0][tid];
        int   bi = sm.r.ri[0][tid];
        #pragma unroll
        for (int t = 1; t < 16; t++) {
            float v = sm.r.rv[t][tid];
            int  ix = sm.r.ri[t][tid];
            if (v < bv || (v == bv && ix < bi)) { bv = v; bi = ix; }
        }
        cand_d[(size_t)ct * NROWS2 + row0 + tid] = bv;
        cand_i[(size_t)ct * NROWS2 + row0 + tid] = bi;
    }
}

// ============================================================================
// Reduce 4 candidates per row -> final code
// ============================================================================
__global__ void vq_reduce_kernel(const float* __restrict__ cand_d,
                                 const int* __restrict__ cand_i,
                                 int* __restrict__ codes)
{
    int row = blockIdx.x * 256 + threadIdx.x;
    float bv = cand_d[row];
    int   bi = cand_i[row];
    #pragma unroll
    for (int ct = 1; ct < 4; ct++) {
        float v = cand_d[(size_t)ct * NROWS2 + row];
        int  ix = cand_i[(size_t)ct * NROWS2 + row];
        if (v < bv || (v == bv && ix < bi)) { bv = v; bi = ix; }
    }
    codes[row] = bi;
}

// ============================================================================
// latent[row] = codebook[codes[row]]  (2 rows per 256-thread block)
// ============================================================================
__global__ void gather_latent_kernel(const int* __restrict__ codes,
                                     const float* __restrict__ cb,
                                     float* __restrict__ latent)
{
    int row  = blockIdx.x * 2 + (threadIdx.x >> 7);
    int lane = threadIdx.x & 127;
    int c = codes[row];
    const float4* src = (const float4*)(cb + (size_t)c * CDIM);
    float4* dst = (float4*)(latent + (size_t)row * CDIM);
    dst[lane] = src[lane];
}

// ============================================================================
// launch
// ============================================================================
extern "C" void kernel_launch(void* const* d_in, const int* in_sizes, int n_in,
                              void* d_out, int out_size)
{
    const float* x    = (const float*)d_in[0];
    const float* ew1  = (const float*)d_in[1];
    const float* eb1  = (const float*)d_in[2];
    const float* ew2  = (const float*)d_in[3];
    const float* eb2  = (const float*)d_in[4];
    const float* ew3  = (const float*)d_in[5];
    const float* eb3  = (const float*)d_in[6];
    const float* cb   = (const float*)d_in[7];
    const float* dw1  = (const float*)d_in[8];
    const float* db1  = (const float*)d_in[9];
    const float* dw2  = (const float*)d_in[10];
    const float* db2  = (const float*)d_in[11];

    float* out        = (float*)d_out;
    float* out_recon  = out;                                     // [8192, 784]
    float* out_obs    = out + (size_t)BROWS * DDIM;              // [131072, 512]
    float* out_latent = out_obs + (size_t)BROWS * CSDIM;         // [131072, 512]

    float *h1, *h2, *cn, *rn, *cd, *tbl; int *codes, *ci;
    cudaGetSymbolAddress((void**)&h1, g_h1);
    cudaGetSymbolAddress((void**)&h2, g_h2);
    cudaGetSymbolAddress((void**)&cn, g_cnorm);
    cudaGetSymbolAddress((void**)&rn, g_rownorm);
    cudaGetSymbolAddress((void**)&cd, g_cand_d);
    cudaGetSymbolAddress((void**)&ci, g_cand_i);
    cudaGetSymbolAddress((void**)&tbl, g_table);
    cudaGetSymbolAddress((void**)&codes, g_codes);

    // codebook row norms + decoder table (independent of encoder chain)
    cnorm_kernel<<<CDIM / 8, 256>>>(cb, cn);
    table_gemm<<<dim3(4, 4, SDIM), 256>>>(cb, dw1, tbl);

    // encoder
    gemm_small<1,1><<<dim3(4, 64), 256>>>(x,  ew1, eb1, h1, HDIM, DDIM, HDIM);
    gemm_small<1,1><<<dim3(4, 64), 256>>>(h1, ew2, eb2, h2, HDIM, HDIM, HDIM);
    gemm_big<0><<<dim3(64, 32), 256>>>(h2, ew3, eb3, out_obs, CSDIM, HDIM);

    // obs row norms, VQ, gather
    rownorm_kernel<<<NROWS2 / 8, 256>>>(out_obs, rn);
    vq_gemm<<<dim3(4, NROWS2 / 256), 256>>>(out_obs, cb, cn, rn, cd, ci);
    vq_reduce_kernel<<<NROWS2 / 256, 256>>>(cd, ci, codes);
    gather_latent_kernel<<<NROWS2 / 2, 256>>>(codes, cb, out_latent);

    // decoder: dec1 = table gather-sum, dec2 = small GEMM
    dec1_gather<<<BROWS / 2, 256>>>(codes, tbl, db1, h1);
    gemm_small<0,1><<<dim3(7, 64), 256>>>(h1, dw2, db2, out_recon, DDIM, HDIM, DDIM);
}